// round 16
// baseline (speedup 1.0000x reference)
#include <cuda_runtime.h>

#define NB   32        // batch
#define NE   200000    // entities
#define NT   1000000   // triples
#define NR   256       // relations
#define DQ   768       // question dim
#define DIN  1280      // DQ + 2*NR
#define NEB  (NE * NB) // 6.4M floats
#define NJ   257       // 256 W_inf rows + 1 W_att row

// ---- device scratch (static; no allocation) ----
__device__ float g_x0T[NEB];           // transposed seed x: [e][b] (active rows)
__device__ float g_xh[3 * NEB];        // hop outputs, entity-major
__device__ float g_y01[NEB];           // a0*x0+a1*x1 (gated; ungated rows unread)
__device__ float g_rT[3 * NR * NB];    // r per hop: [j][b]
__device__ float g_c[3 * NB];          // attention logits per hop
__device__ unsigned g_lm[4 * NE];      // per-entity 32-bit lane-activity mask per hop

// ================= phase 1: transpose + big zeroing + gemm_base =============
#define B_GB NJ                                // 257 (one block per output row)
#define B_TX (NE / 32)                         // 6250
#define B_ZX ((3 * NEB / 4 + 1023) / 1024)     // 4688
#define B_ZM ((3 * NE + 255) / 256)            // 2344
#define B_P1 (B_GB + B_TX + B_ZX + B_ZM)

__global__ void k_phase1(const float* __restrict__ x,
                         const float* __restrict__ h_q,
                         const float* __restrict__ W_inf,
                         const float* __restrict__ W_att) {
    int bid = blockIdx.x;
    int tid = threadIdx.x;
    int lane = tid & 31, ty = tid >> 5;

    if (bid < B_GB) {
        // ---- gemm_base: r_0/c_0 = h_q @ [W_inf; W_att][:, :768].T ----
        // One block per j; warp ty covers d in [ty*96, ty*96+96); thread lane=b
        // reads its own h_q row (L1/L2-resident across all 257 blocks).
        __shared__ float sr[8][32];
        int j = bid;
        const float* w = (j == 256) ? W_att : W_inf + (size_t)j * DIN;
        const float* hrow = h_q + (size_t)lane * DQ;
        int d0 = ty * 96;
        float a = 0.f;
#pragma unroll
        for (int d = d0; d < d0 + 96; d += 4) {
            float4 hv = *reinterpret_cast<const float4*>(&hrow[d]);
            a += hv.x * w[d] + hv.y * w[d + 1] + hv.z * w[d + 2] + hv.w * w[d + 3];
        }
        sr[ty][lane] = a;
        __syncthreads();
        if (ty == 0) {
            float t = 0.f;
#pragma unroll
            for (int k = 0; k < 8; k++) t += sr[k][lane];
            if (j == 256) g_c[lane] = t;               // direct store, no atomic
            else          g_rT[j * NB + lane] = t;
        }
    } else if (bid < B_GB + B_TX) {
        // ---- transpose x (B x NE) -> (NE x B), sparse writes + hop-0 lane mask
        __shared__ float s[32][33];
        int cbase = (bid - B_GB) * 32;
#pragma unroll
        for (int row = ty; row < 32; row += 8)          // row = b
            s[row][lane] = x[(size_t)row * NE + cbase + lane];
        __syncthreads();
#pragma unroll
        for (int row = ty; row < 32; row += 8) {        // row = entity offset
            float v = s[lane][row];                     // lane = b
            unsigned b = __ballot_sync(0xffffffffu, v != 0.0f);
            if (b) g_x0T[(size_t)(cbase + row) * NB + lane] = v;
            if (lane == 0) g_lm[cbase + row] = b;       // exact hop-0 lane mask
        }
    } else if (bid < B_GB + B_TX + B_ZX) {
        // ---- zero g_xh (4 float4 per thread): also L2-prefetches scatter dests
        int base = (bid - B_GB - B_TX) * 1024 + tid;
        const int nq = 3 * NEB / 4;
#pragma unroll
        for (int k = 0; k < 4; k++) {
            int i = base + k * 256;
            if (i < nq)
                reinterpret_cast<float4*>(g_xh)[i] = make_float4(0.f, 0.f, 0.f, 0.f);
        }
    } else {
        // ---- zero lm[1..3] ----
        int i = (bid - B_GB - B_TX - B_ZX) * 256 + tid;
        if (i < 3 * NE) g_lm[NE + i] = 0u;
    }
}

// ================= shared device pieces for phases 2-4 ======================
// full hop gemm: out_hop = hop0_out + r_parts @ W[:, 768:768+hop*256].T
// One block per j; 8 warps split the k-range (32*hop k's each); direct store.
__device__ __forceinline__ void gemm_hop_full(const float* __restrict__ W_inf,
                                              const float* __restrict__ W_att,
                                              int hop, int j, int lane, int ty) {
    __shared__ float s[8][32];
    const float* w = (j == 256) ? W_att : W_inf + (size_t)j * DIN;
    int kt = hop << 5;                 // 32 (hop1) or 64 (hop2) per warp
    int kk0 = ty * kt;
    float a0 = 0.f, a1 = 0.f;
#pragma unroll 8
    for (int k = 0; k < kt; k += 2) {
        int kk = kk0 + k;
        int seg = kk >> 8;             // k-pairs never straddle a segment
        int within = kk & 255;
        const float* rsrc = g_rT + (hop - 1 - seg) * NR * NB;
        a0 += rsrc[within * NB + lane] * w[DQ + kk];
        a1 += rsrc[(within + 1) * NB + lane] * w[DQ + kk + 1];
    }
    s[ty][lane] = a0 + a1;
    __syncthreads();
    if (ty == 0) {
        float t = (j == 256) ? g_c[lane] : g_rT[j * NB + lane];  // hop-0 base
#pragma unroll
        for (int k = 0; k < 8; k++) t += s[k][lane];
        if (j == 256) g_c[hop * NB + lane] = t;        // direct store
        else          g_rT[hop * NR * NB + j * NB + lane] = t;
    }
}

// scatter: lane-mask-gated gather*relation -> red.v4 scatter; produces lm[hop+1].
__device__ __forceinline__ void scatter_body(const int* __restrict__ subj,
                                             const int* __restrict__ rel,
                                             const int* __restrict__ obj,
                                             int hop, int sblk, int tid) {
    const float* __restrict__ rT = g_rT + hop * NR * NB;
    const float* __restrict__ xin = (hop == 0) ? g_x0T : (g_xh + (hop - 1) * NEB);
    float* xout = g_xh + hop * NEB;
    const unsigned* __restrict__ lmin = g_lm + hop * NE;
    unsigned* lmout = g_lm + (hop + 1) * NE;

    int lane = tid & 31;
    int t8 = lane >> 2;            // 0..7: triple slot this iteration
    int q2 = lane & 3;             // handles quads 2*q2 and 2*q2+1
    int t = sblk * 256 + tid;

    int s_i = 0, r_i = 0, o_i = 0;
    unsigned lm_i = 0;
    if (t < NT) {
        s_i = subj[t];
        lm_i = lmin[s_i];
        if (lm_i) { r_i = rel[t]; o_i = obj[t]; }
    }
    unsigned bal = __ballot_sync(0xffffffffu, lm_i != 0);
    while (bal) {
        int myi = __fns(bal, 0, t8 + 1);       // (t8+1)-th set bit, or -1
        int i7  = __fns(bal, 0, 8);            // 8th set bit (for clearing)
        bool on = (myi >= 0);
        int src = on ? myi : 0;
        int s = __shfl_sync(0xffffffffu, s_i, src);
        int r = __shfl_sync(0xffffffffu, r_i, src);
        int o = __shfl_sync(0xffffffffu, o_i, src);
        unsigned lmw = __shfl_sync(0xffffffffu, lm_i, src);
        unsigned m8 = 0;
        if (on) {
#pragma unroll
            for (int h = 0; h < 2; h++) {
                int quad = q2 * 2 + h;
                unsigned nib = (lmw >> (quad * 4)) & 0xFu;
                if (nib) {
                    float4 xv = *reinterpret_cast<const float4*>(
                        &xin[(size_t)s * NB + quad * 4]);
                    float4 rv = *reinterpret_cast<const float4*>(
                        &rT[r * NB + quad * 4]);
                    float4 p;
                    p.x = xv.x * rv.x; p.y = xv.y * rv.y;
                    p.z = xv.z * rv.z; p.w = xv.w * rv.w;
                    unsigned m4 = (p.x != 0.f) | ((p.y != 0.f) << 1) |
                                  ((p.z != 0.f) << 2) | ((p.w != 0.f) << 3);
                    if (m4) {
                        float* dst = &xout[(size_t)o * NB + quad * 4];
                        asm volatile("red.global.add.v4.f32 [%0], {%1,%2,%3,%4};"
                                     :: "l"(dst), "f"(p.x), "f"(p.y),
                                        "f"(p.z), "f"(p.w)
                                     : "memory");
                        m8 |= m4 << (quad * 4);
                    }
                }
            }
        }
        m8 |= __shfl_down_sync(0xffffffffu, m8, 2, 4);
        m8 |= __shfl_down_sync(0xffffffffu, m8, 1, 4);
        if (on && q2 == 0 && m8)
            atomicOr(&lmout[o], m8);
        if (i7 < 0) bal = 0;
        else        bal &= ~((2u << i7) - 1);
    }
}

// softmax coefficients from g_c (per-lane b = lane)
__device__ __forceinline__ void softmax3(int lane, float& a0, float& a1, float& a2) {
    float c0 = g_c[lane], c1 = g_c[NB + lane], c2 = g_c[2 * NB + lane];
    float m = fmaxf(c0, fmaxf(c1, c2));
    float e0 = expf(c0 - m), e1 = expf(c1 - m), e2 = expf(c2 - m);
    float inv = 1.0f / (e0 + e1 + e2);
    a0 = e0 * inv; a1 = e1 * inv; a2 = e2 * inv;
}

#define B_SC ((NT + 255) / 256)   // 3907 scatter blocks
#define B_CB (NE / 32)            // 6250 combine blocks

// ============ phase 2: gemm_hop1 (NJ blocks) + scatter hop0 =================
__global__ void k_phase2(const int* __restrict__ subj, const int* __restrict__ rel,
                         const int* __restrict__ obj,
                         const float* __restrict__ W_inf,
                         const float* __restrict__ W_att) {
    int bid = blockIdx.x, tid = threadIdx.x;
    if (bid < NJ)
        gemm_hop_full(W_inf, W_att, 1, bid, tid & 31, tid >> 5);
    else
        scatter_body(subj, rel, obj, 0, bid - NJ, tid);
}

// ============ phase 3: gemm_hop2 (NJ blocks) + scatter hop1 =================
__global__ void k_phase3(const int* __restrict__ subj, const int* __restrict__ rel,
                         const int* __restrict__ obj,
                         const float* __restrict__ W_inf,
                         const float* __restrict__ W_att) {
    int bid = blockIdx.x, tid = threadIdx.x;
    if (bid < NJ)
        gemm_hop_full(W_inf, W_att, 2, bid, tid & 31, tid >> 5);
    else
        scatter_body(subj, rel, obj, 1, bid - NJ, tid);
}

// ====== phase 4: scatter hop2 + combine01 (y01 = a0*x0 + a1*x1, gated) ======
__global__ void k_phase4(const int* __restrict__ subj, const int* __restrict__ rel,
                         const int* __restrict__ obj) {
    int bid = blockIdx.x, tid = threadIdx.x;
    if (bid < B_SC) {
        scatter_body(subj, rel, obj, 2, bid, tid);
        return;
    }
    int lane = tid & 31, ty = tid >> 5;
    float a0, a1, a2;
    softmax3(lane, a0, a1, a2);
    int ebase = (bid - B_SC) * 32;
#pragma unroll
    for (int row = ty; row < 32; row += 8) {            // row = e offset, lane = b
        int e = ebase + row;
        unsigned m1 = g_lm[NE + e], m2 = g_lm[2 * NE + e];
        if (m1 | m2) {
            int idx = e * NB + lane;
            float v = 0.f;
            if (m1) v += a0 * g_xh[idx];
            if (m2) v += a1 * g_xh[NEB + idx];
            g_y01[idx] = v;
        }
    }
}

// ============ phase 5: out = transpose(y01 + a2*x2) =========================
__global__ void k_combine2(float* __restrict__ out) {
    __shared__ float s[32][33];
    int lane = threadIdx.x & 31, ty = threadIdx.x >> 5;
    float a0, a1, a2;
    softmax3(lane, a0, a1, a2);

    int ebase = blockIdx.x * 32;
#pragma unroll
    for (int row = ty; row < 32; row += 8) {           // row = e offset, lane = b
        int e = ebase + row;
        int idx = e * NB + lane;
        float v = 0.f;
        if (g_lm[NE + e] | g_lm[2 * NE + e]) v = g_y01[idx];
        if (g_lm[3 * NE + e]) v += a2 * g_xh[2 * NEB + idx];
        s[row][lane] = v;
    }
    __syncthreads();
#pragma unroll
    for (int row = ty; row < 32; row += 8)             // row = b, lane = e offset
        out[(size_t)row * NE + ebase + lane] = s[lane][row];
}

extern "C" void kernel_launch(void* const* d_in, const int* in_sizes, int n_in,
                              void* d_out, int out_size) {
    const float* x     = (const float*)d_in[0];
    const float* h_q   = (const float*)d_in[1];
    const float* W_inf = (const float*)d_in[2];
    const float* W_att = (const float*)d_in[3];
    const int*   subj  = (const int*)d_in[4];
    const int*   rel   = (const int*)d_in[5];
    const int*   obj   = (const int*)d_in[6];
    float* out = (float*)d_out;

    k_phase1<<<B_P1, 256>>>(x, h_q, W_inf, W_att);
    k_phase2<<<NJ + B_SC, 256>>>(subj, rel, obj, W_inf, W_att);
    k_phase3<<<NJ + B_SC, 256>>>(subj, rel, obj, W_inf, W_att);
    k_phase4<<<B_SC + B_CB, 256>>>(subj, rel, obj);
    k_combine2<<<B_CB, 256>>>(out);
}

// round 17
// speedup vs baseline: 1.0975x; 1.0975x over previous
#include <cuda_runtime.h>

#define NB   32        // batch
#define NE   200000    // entities
#define NT   1000000   // triples
#define NR   256       // relations
#define DQ   768       // question dim
#define DIN  1280      // DQ + 2*NR
#define NEB  (NE * NB) // 6.4M floats
#define NJ   257       // 256 W_inf rows + 1 W_att row

// ---- device scratch (static; no allocation) ----
__device__ float g_x0T[NEB];           // transposed seed x: [e][b] (active rows)
__device__ float g_xh[3 * NEB];        // hop outputs, entity-major
__device__ float g_rT[3 * NR * NB];    // r per hop: [j][b]
__device__ float g_c[3 * NB];          // attention logits per hop
__device__ unsigned g_lm[4 * NE];      // per-entity 32-bit lane-activity mask per hop

// ================= phase 1: transpose + big zeroing + gemm_base =============
#define B_GB NJ                                // 257 (one block per output row)
#define B_TX (NE / 32)                         // 6250
#define B_ZX ((3 * NEB / 4 + 1023) / 1024)     // 4688
#define B_ZM ((3 * NE + 255) / 256)            // 2344
#define B_P1 (B_GB + B_TX + B_ZX + B_ZM)

__global__ void k_phase1(const float* __restrict__ x,
                         const float* __restrict__ h_q,
                         const float* __restrict__ W_inf,
                         const float* __restrict__ W_att) {
    int bid = blockIdx.x;
    int tid = threadIdx.x;
    int lane = tid & 31, ty = tid >> 5;

    if (bid < B_GB) {
        // ---- gemm_base: r_0/c_0 = h_q @ [W_inf; W_att][:, :768].T ----
        // One block per j; warp ty covers d in [ty*96, +96); lane = b reads its
        // own h_q row (L1-resident across warps). Direct store, no atomics.
        __shared__ float sr[8][32];
        int j = bid;
        const float* w = (j == 256) ? W_att : W_inf + (size_t)j * DIN;
        const float* hrow = h_q + (size_t)lane * DQ;
        int d0 = ty * 96;
        float a = 0.f;
#pragma unroll
        for (int d = d0; d < d0 + 96; d += 4) {
            float4 hv = *reinterpret_cast<const float4*>(&hrow[d]);
            a += hv.x * w[d] + hv.y * w[d + 1] + hv.z * w[d + 2] + hv.w * w[d + 3];
        }
        sr[ty][lane] = a;
        __syncthreads();
        if (ty == 0) {
            float t = 0.f;
#pragma unroll
            for (int k = 0; k < 8; k++) t += sr[k][lane];
            if (j == 256) g_c[lane] = t;
            else          g_rT[j * NB + lane] = t;
        }
    } else if (bid < B_GB + B_TX) {
        // ---- transpose x (B x NE) -> (NE x B), sparse writes + hop-0 lane mask
        __shared__ float s[32][33];
        int cbase = (bid - B_GB) * 32;
#pragma unroll
        for (int row = ty; row < 32; row += 8)          // row = b
            s[row][lane] = x[(size_t)row * NE + cbase + lane];
        __syncthreads();
#pragma unroll
        for (int row = ty; row < 32; row += 8) {        // row = entity offset
            float v = s[lane][row];                     // lane = b
            unsigned b = __ballot_sync(0xffffffffu, v != 0.0f);
            if (b) g_x0T[(size_t)(cbase + row) * NB + lane] = v;
            if (lane == 0) g_lm[cbase + row] = b;       // exact hop-0 lane mask
        }
    } else if (bid < B_GB + B_TX + B_ZX) {
        // ---- zero g_xh (4 float4 per thread): also L2-prefetches scatter dests
        int base = (bid - B_GB - B_TX) * 1024 + tid;
        const int nq = 3 * NEB / 4;
#pragma unroll
        for (int k = 0; k < 4; k++) {
            int i = base + k * 256;
            if (i < nq)
                reinterpret_cast<float4*>(g_xh)[i] = make_float4(0.f, 0.f, 0.f, 0.f);
        }
    } else {
        // ---- zero lm[1..3] ----
        int i = (bid - B_GB - B_TX - B_ZX) * 256 + tid;
        if (i < 3 * NE) g_lm[NE + i] = 0u;
    }
}

// ================= shared device pieces for phases 2-4 ======================
// full hop gemm: out_hop = hop0_out + r_parts @ W[:, 768:768+hop*256].T
// One block per j; 8 warps split the k-range; direct store, no atomics.
__device__ __forceinline__ void gemm_hop_full(const float* __restrict__ W_inf,
                                              const float* __restrict__ W_att,
                                              int hop, int j, int lane, int ty) {
    __shared__ float s[8][32];
    const float* w = (j == 256) ? W_att : W_inf + (size_t)j * DIN;
    int kt = hop << 5;                 // 32 (hop1) or 64 (hop2) per warp
    int kk0 = ty * kt;
    float a0 = 0.f, a1 = 0.f;
#pragma unroll 8
    for (int k = 0; k < kt; k += 2) {
        int kk = kk0 + k;
        int seg = kk >> 8;             // k-pairs never straddle a segment
        int within = kk & 255;
        const float* rsrc = g_rT + (hop - 1 - seg) * NR * NB;
        a0 += rsrc[within * NB + lane] * w[DQ + kk];
        a1 += rsrc[(within + 1) * NB + lane] * w[DQ + kk + 1];
    }
    s[ty][lane] = a0 + a1;
    __syncthreads();
    if (ty == 0) {
        float t = (j == 256) ? g_c[lane] : g_rT[j * NB + lane];  // hop-0 base
#pragma unroll
        for (int k = 0; k < 8; k++) t += s[k][lane];
        if (j == 256) g_c[hop * NB + lane] = t;
        else          g_rT[hop * NR * NB + j * NB + lane] = t;
    }
}

// scatter: lane-mask-gated gather*relation -> red.v4 scatter; produces lm[hop+1].
__device__ __forceinline__ void scatter_body(const int* __restrict__ subj,
                                             const int* __restrict__ rel,
                                             const int* __restrict__ obj,
                                             int hop, int sblk, int tid) {
    const float* __restrict__ rT = g_rT + hop * NR * NB;
    const float* __restrict__ xin = (hop == 0) ? g_x0T : (g_xh + (hop - 1) * NEB);
    float* xout = g_xh + hop * NEB;
    const unsigned* __restrict__ lmin = g_lm + hop * NE;
    unsigned* lmout = g_lm + (hop + 1) * NE;

    int lane = tid & 31;
    int t8 = lane >> 2;            // 0..7: triple slot this iteration
    int q2 = lane & 3;             // handles quads 2*q2 and 2*q2+1
    int t = sblk * 256 + tid;

    int s_i = 0, r_i = 0, o_i = 0;
    unsigned lm_i = 0;
    if (t < NT) {
        s_i = subj[t];
        lm_i = lmin[s_i];
        if (lm_i) { r_i = rel[t]; o_i = obj[t]; }
    }
    unsigned bal = __ballot_sync(0xffffffffu, lm_i != 0);
    while (bal) {
        int myi = __fns(bal, 0, t8 + 1);       // (t8+1)-th set bit, or -1
        int i7  = __fns(bal, 0, 8);            // 8th set bit (for clearing)
        bool on = (myi >= 0);
        int src = on ? myi : 0;
        int s = __shfl_sync(0xffffffffu, s_i, src);
        int r = __shfl_sync(0xffffffffu, r_i, src);
        int o = __shfl_sync(0xffffffffu, o_i, src);
        unsigned lmw = __shfl_sync(0xffffffffu, lm_i, src);
        unsigned m8 = 0;
        if (on) {
#pragma unroll
            for (int h = 0; h < 2; h++) {
                int quad = q2 * 2 + h;
                unsigned nib = (lmw >> (quad * 4)) & 0xFu;
                if (nib) {
                    float4 xv = *reinterpret_cast<const float4*>(
                        &xin[(size_t)s * NB + quad * 4]);
                    float4 rv = *reinterpret_cast<const float4*>(
                        &rT[r * NB + quad * 4]);
                    float4 p;
                    p.x = xv.x * rv.x; p.y = xv.y * rv.y;
                    p.z = xv.z * rv.z; p.w = xv.w * rv.w;
                    unsigned m4 = (p.x != 0.f) | ((p.y != 0.f) << 1) |
                                  ((p.z != 0.f) << 2) | ((p.w != 0.f) << 3);
                    if (m4) {
                        float* dst = &xout[(size_t)o * NB + quad * 4];
                        asm volatile("red.global.add.v4.f32 [%0], {%1,%2,%3,%4};"
                                     :: "l"(dst), "f"(p.x), "f"(p.y),
                                        "f"(p.z), "f"(p.w)
                                     : "memory");
                        m8 |= m4 << (quad * 4);
                    }
                }
            }
        }
        m8 |= __shfl_down_sync(0xffffffffu, m8, 2, 4);
        m8 |= __shfl_down_sync(0xffffffffu, m8, 1, 4);
        if (on && q2 == 0 && m8)
            atomicOr(&lmout[o], m8);
        if (i7 < 0) bal = 0;
        else        bal &= ~((2u << i7) - 1);
    }
}

#define B_SC ((NT + 255) / 256)   // 3907 scatter blocks

// ============ phase 2: gemm_hop1 (NJ blocks) + scatter hop0 =================
__global__ void k_phase2(const int* __restrict__ subj, const int* __restrict__ rel,
                         const int* __restrict__ obj,
                         const float* __restrict__ W_inf,
                         const float* __restrict__ W_att) {
    int bid = blockIdx.x, tid = threadIdx.x;
    if (bid < NJ)
        gemm_hop_full(W_inf, W_att, 1, bid, tid & 31, tid >> 5);
    else
        scatter_body(subj, rel, obj, 0, bid - NJ, tid);
}

// ============ phase 3: gemm_hop2 (NJ blocks) + scatter hop1 =================
__global__ void k_phase3(const int* __restrict__ subj, const int* __restrict__ rel,
                         const int* __restrict__ obj,
                         const float* __restrict__ W_inf,
                         const float* __restrict__ W_att) {
    int bid = blockIdx.x, tid = threadIdx.x;
    if (bid < NJ)
        gemm_hop_full(W_inf, W_att, 2, bid, tid & 31, tid >> 5);
    else
        scatter_body(subj, rel, obj, 1, bid - NJ, tid);
}

// ============ phase 4: scatter hop2 =========================================
__global__ void k_phase4(const int* __restrict__ subj, const int* __restrict__ rel,
                         const int* __restrict__ obj) {
    scatter_body(subj, rel, obj, 2, blockIdx.x, threadIdx.x);
}

// ============ phase 5: softmax + masked combine + transpose out =============
__global__ void k_combine(float* __restrict__ out) {
    __shared__ float s[32][33];
    int lane = threadIdx.x & 31, ty = threadIdx.x >> 5;
    float c0 = g_c[lane], c1 = g_c[NB + lane], c2 = g_c[2 * NB + lane];
    float m = fmaxf(c0, fmaxf(c1, c2));
    float e0 = expf(c0 - m), e1 = expf(c1 - m), e2 = expf(c2 - m);
    float inv = 1.0f / (e0 + e1 + e2);
    float a0 = e0 * inv, a1 = e1 * inv, a2 = e2 * inv;

    int ebase = blockIdx.x * 32;
#pragma unroll
    for (int row = ty; row < 32; row += 8) {           // row = e offset, lane = b
        int e = ebase + row;
        int idx = e * NB + lane;
        float v = 0.f;
        if (g_lm[NE + e])     v += a0 * g_xh[idx];
        if (g_lm[2 * NE + e]) v += a1 * g_xh[NEB + idx];
        if (g_lm[3 * NE + e]) v += a2 * g_xh[2 * NEB + idx];
        s[row][lane] = v;
    }
    __syncthreads();
#pragma unroll
    for (int row = ty; row < 32; row += 8)             // row = b, lane = e offset
        out[(size_t)row * NE + ebase + lane] = s[lane][row];
}

extern "C" void kernel_launch(void* const* d_in, const int* in_sizes, int n_in,
                              void* d_out, int out_size) {
    const float* x     = (const float*)d_in[0];
    const float* h_q   = (const float*)d_in[1];
    const float* W_inf = (const float*)d_in[2];
    const float* W_att = (const float*)d_in[3];
    const int*   subj  = (const int*)d_in[4];
    const int*   rel   = (const int*)d_in[5];
    const int*   obj   = (const int*)d_in[6];
    float* out = (float*)d_out;

    k_phase1<<<B_P1, 256>>>(x, h_q, W_inf, W_att);
    k_phase2<<<NJ + B_SC, 256>>>(subj, rel, obj, W_inf, W_att);
    k_phase3<<<NJ + B_SC, 256>>>(subj, rel, obj, W_inf, W_att);
    k_phase4<<<B_SC, 256>>>(subj, rel, obj);
    k_combine<<<NE / 32, 256>>>(out);
}